// round 7
// baseline (speedup 1.0000x reference)
#include <cuda_runtime.h>
#include <cuda_bf16.h>

// Scratch (no allocations allowed -> __device__ globals)
__device__ float g_LU[2][128 * 128];     // in-place LU factors of (I - A/2)
__device__ float g_QT[2][128 * 128];     // QT[m][i*128+j] = Q[j][i]  (v_new = v @ Q^T)
__device__ float g_table[4096 * 128];    // pathemb table for every position value

// ---------------------------------------------------------------------------
// Kernel 1: LU factorization (no pivoting; M = I - A/2 has SPD symmetric part)
// 2 blocks (one per primitive matrix), 1024 threads, matrix in registers.
// Thread (tr = t&31, tc = t>>5) owns rows {tr+32s} x cols {4tc..4tc+3}.
// ---------------------------------------------------------------------------
__global__ __launch_bounds__(1024, 1) void lu_kernel(const float* __restrict__ X) {
    const int m = blockIdx.x;
    const float* Xm = X + m * 128 * 128;
    const int t = threadIdx.x;
    const int tr = t & 31;
    const int tc = t >> 5;

    float reg[4][4];
#pragma unroll
    for (int s = 0; s < 4; s++) {
        const int r = tr + 32 * s;
#pragma unroll
        for (int q = 0; q < 4; q++) {
            const int c = 4 * tc + q;
            float a = (r > c) ? Xm[r * 128 + c] : ((r < c) ? -Xm[c * 128 + r] : 0.0f);
            reg[s][q] = ((r == c) ? 1.0f : 0.0f) - 0.5f * a;
        }
    }

    __shared__ float colbuf[128];
    __shared__ float rowbuf[128];

    for (int k = 0; k < 128; k++) {
        __syncthreads();
        // stage column k (current Schur values)
        if ((k >> 2) == tc) {
            const int q = k & 3;
#pragma unroll
            for (int s = 0; s < 4; s++) colbuf[tr + 32 * s] = reg[s][q];
        }
        // stage row k
        if ((k & 31) == tr) {
            const int s = k >> 5;
#pragma unroll
            for (int q = 0; q < 4; q++) rowbuf[4 * tc + q] = reg[s][q];
        }
        __syncthreads();
        const float pinv = 1.0f / rowbuf[k];
#pragma unroll
        for (int s = 0; s < 4; s++) {
            const int r = tr + 32 * s;
            if (r > k) {
                const float l = colbuf[r] * pinv;
#pragma unroll
                for (int q = 0; q < 4; q++) {
                    const int c = 4 * tc + q;
                    if (c > k)      reg[s][q] -= l * rowbuf[c];
                    else if (c == k) reg[s][q] = l;   // store L in place
                }
            }
        }
    }
    __syncthreads();
#pragma unroll
    for (int s = 0; s < 4; s++) {
        const int r = tr + 32 * s;
#pragma unroll
        for (int q = 0; q < 4; q++)
            g_LU[m][r * 128 + 4 * tc + q] = reg[s][q];
    }
}

// ---------------------------------------------------------------------------
// Kernel 2: 256 independent warp-level triangular solves -> Q^T
// Warp w solves M q = R[:, j] (R = I + A/2), writes QT row j.
// ---------------------------------------------------------------------------
__global__ __launch_bounds__(128) void solve_kernel(const float* __restrict__ X) {
    const int wid  = blockIdx.x * (blockDim.x >> 5) + (threadIdx.x >> 5);  // 0..255
    const int lane = threadIdx.x & 31;
    const int m = wid >> 7;
    const int j = wid & 127;
    const float* Xm = X + m * 128 * 128;
    const float* LU = g_LU[m];

    float y[4];
#pragma unroll
    for (int s = 0; s < 4; s++) {
        const int i = lane + 32 * s;
        float a = (i > j) ? Xm[i * 128 + j] : ((i < j) ? -Xm[j * 128 + i] : 0.0f);
        y[s] = ((i == j) ? 1.0f : 0.0f) + 0.5f * a;
    }
    // forward: L z = r (unit lower)
    for (int k = 0; k < 127; k++) {
        const float yk = __shfl_sync(0xffffffffu, y[k >> 5], k & 31);
#pragma unroll
        for (int s = 0; s < 4; s++) {
            const int i = lane + 32 * s;
            if (i > k) y[s] -= LU[i * 128 + k] * yk;
        }
    }
    // backward: U q = z
    for (int k = 127; k >= 1; k--) {
        float yk = __shfl_sync(0xffffffffu, y[k >> 5], k & 31);
        yk = yk / LU[k * 128 + k];
        if (lane == (k & 31)) y[k >> 5] = yk;
#pragma unroll
        for (int s = 0; s < 4; s++) {
            const int i = lane + 32 * s;
            if (i < k) y[s] -= LU[i * 128 + k] * yk;
        }
    }
    if (lane == 0) y[0] = y[0] / LU[0];
    // QT[m][j][i] = Q[j][i] = q_i   (coalesced row write)
#pragma unroll
    for (int s = 0; s < 4; s++)
        g_QT[m][j * 128 + lane + 32 * s] = y[s];
}

// ---------------------------------------------------------------------------
// Kernel 3: path-embedding table for every value p in [0, 4096).
// Recursion: pathemb(v + (b+1)*msb(v)) = pathemb(v) @ Q[b]^T.
// Block g owns level-8 root r=128+g and all p>=256 with (p&127)==g.
// Q0^T,Q1^T in SMEM (128 KB), 512 threads = 4 parallel matvec lanes.
// ---------------------------------------------------------------------------
#define TBL_SMEM_FLOATS (2 * 16384 + 2 * 2048)
__global__ __launch_bounds__(512, 1) void table_kernel(const float* __restrict__ identity) {
    extern __shared__ float sm[];
    float* Q0s  = sm;
    float* Q1s  = sm + 16384;
    float* bufA = sm + 32768;
    float* bufB = sm + 34816;
    __shared__ int pv[2][16];

    const int t = threadIdx.x;
    const int g = blockIdx.x;      // 0..127
    const int l = t >> 7;          // matvec lane 0..3
    const int j = t & 127;

    // load both Q^T matrices into smem
    {
        const float4* src = (const float4*)g_QT;
        float4* dst = (float4*)sm;
        for (int i = t; i < 8192; i += 512) dst[i] = src[i];
    }
    if (t < 128) bufA[j] = identity[j];
    if (g == 0 && t < 128) {                 // p = 0, 1 -> identity (empty path)
        g_table[0 + j]   = identity[j];
        g_table[128 + j] = identity[j];
    }
    __syncthreads();

    float* cur = bufA;
    float* nxt = bufB;

    // root path: 7 matvecs, writing ancestors at levels 2..8
    for (int d = 0; d < 7; d++) {
        if (t < 128) {
            const int b = (g >> d) & 1;
            const float* Qp = b ? Q1s : Q0s;
            float a0 = 0.f, a1 = 0.f, a2 = 0.f, a3 = 0.f;
            for (int i = 0; i < 128; i += 4) {
                const float4 vv = *(const float4*)(cur + i);
                a0 += vv.x * Qp[(i + 0) * 128 + j];
                a1 += vv.y * Qp[(i + 1) * 128 + j];
                a2 += vv.z * Qp[(i + 2) * 128 + j];
                a3 += vv.w * Qp[(i + 3) * 128 + j];
            }
            const float acc = (a0 + a1) + (a2 + a3);
            nxt[j] = acc;
            const int p = (g & ((2 << d) - 1)) | (2 << d);
            g_table[p * 128 + j] = acc;      // identical across blocks sharing ancestor
        }
        __syncthreads();
        float* tmp = cur; cur = nxt; nxt = tmp;
    }
    if (t == 0) pv[0][0] = 128 + g;
    __syncthreads();

    int cnt = 1, msb = 128, sel = 0;
    for (int lvl = 0; lvl < 4; lvl++) {      // levels 9..12
        const int nch = cnt * 2;
        for (int cb = 0; cb < nch; cb += 4) {
            const int c = cb + l;
            if (c < nch) {
                const int par = c >> 1;
                const int b   = c & 1;
                const int pc  = pv[sel][par] + (b + 1) * msb;
                const float* Qp = b ? Q1s : Q0s;
                const float* vp = cur + par * 128;
                float a0 = 0.f, a1 = 0.f, a2 = 0.f, a3 = 0.f;
                for (int i = 0; i < 128; i += 4) {
                    const float4 vv = *(const float4*)(vp + i);
                    a0 += vv.x * Qp[(i + 0) * 128 + j];
                    a1 += vv.y * Qp[(i + 1) * 128 + j];
                    a2 += vv.z * Qp[(i + 2) * 128 + j];
                    a3 += vv.w * Qp[(i + 3) * 128 + j];
                }
                const float acc = (a0 + a1) + (a2 + a3);
                nxt[c * 128 + j] = acc;
                g_table[pc * 128 + j] = acc;
                if (j == 0) pv[sel ^ 1][c] = pc;
            }
        }
        __syncthreads();
        float* tmp = cur; cur = nxt; nxt = tmp;
        sel ^= 1; cnt = nch; msb <<= 1;
    }
}

// ---------------------------------------------------------------------------
// Kernel 4: final embedding assembly. One warp per token, float4 stores.
// out[tok] = [ content(128) | pos_enc(128) ], 128 MB write (HBM-bound).
// ---------------------------------------------------------------------------
__global__ __launch_bounds__(256) void out_kernel(const int* __restrict__ tt,
                                                  const int* __restrict__ tv,
                                                  const int* __restrict__ np,
                                                  const float* __restrict__ ew,
                                                  float* __restrict__ out) {
    const int warp = threadIdx.x >> 5;
    const int lane = threadIdx.x & 31;
    const int tok  = blockIdx.x * 8 + warp;      // < 131072

    const int ty  = tt[tok];
    const int val = tv[tok];
    const int pos = np[tok];

    const float4 pv4 = *(const float4*)(g_table + pos * 128 + lane * 4);

    float4 cv;
    if (ty == 4) {
        int idx = val < 0 ? 0 : (val > 4095 ? 4095 : val);
        cv = *(const float4*)(g_table + idx * 128 + lane * 4);
    } else if (ty == 1) {
        cv = *(const float4*)(ew + (val + 1) * 128 + lane * 4);
    } else if (ty == 2) {
        cv = *(const float4*)(ew + (val + 5) * 128 + lane * 4);
    } else if (ty == 0) {
        cv = *(const float4*)(ew + lane * 4);
    } else if (ty == 3 && val == -1) {
        cv = *(const float4*)(ew + 10 * 128 + lane * 4);
    } else {
        cv = make_float4(0.f, 0.f, 0.f, 0.f);
    }

    float* o = out + (size_t)tok * 256;
    *(float4*)(o + lane * 4)       = cv;
    *(float4*)(o + 128 + lane * 4) = pv4;
}

// ---------------------------------------------------------------------------
extern "C" void kernel_launch(void* const* d_in, const int* in_sizes, int n_in,
                              void* d_out, int out_size) {
    const int*   tt    = (const int*)d_in[0];   // token_types   [32,4096]
    const int*   tv    = (const int*)d_in[1];   // token_values  [32,4096]
    const int*   np    = (const int*)d_in[2];   // node_positions[32,4096]
    const float* prim  = (const float*)d_in[3]; // primitives    [2,128,128]
    const float* ident = (const float*)d_in[4]; // identity      [1,128]
    const float* ew    = (const float*)d_in[5]; // embed_weight  [11,128]
    float* out = (float*)d_out;

    cudaFuncSetAttribute(table_kernel, cudaFuncAttributeMaxDynamicSharedMemorySize,
                         TBL_SMEM_FLOATS * (int)sizeof(float));

    lu_kernel<<<2, 1024>>>(prim);
    solve_kernel<<<64, 128>>>(prim);
    table_kernel<<<128, 512, TBL_SMEM_FLOATS * sizeof(float)>>>(ident);
    out_kernel<<<16384, 256>>>(tt, tv, np, ew, out);
}